// round 10
// baseline (speedup 1.0000x reference)
#include <cuda_runtime.h>
#include <math.h>
#include <stdint.h>

#define BB 2048
typedef unsigned long long ull;

// ---------------- f32x2 packed-math helpers ----------------
__device__ __forceinline__ ull dup2(float v) {
    unsigned x = __float_as_uint(v); ull r;
    asm("mov.b64 %0, {%1, %1};" : "=l"(r) : "r"(x));
    return r;
}
__device__ __forceinline__ ull pack2(float a, float b) {
    unsigned x = __float_as_uint(a), y = __float_as_uint(b); ull r;
    asm("mov.b64 %0, {%1, %2};" : "=l"(r) : "r"(x), "r"(y));
    return r;
}
__device__ __forceinline__ void fma2(ull& d, ull a, ull b) {
    asm("fma.rn.f32x2 %0, %1, %2, %0;" : "+l"(d) : "l"(a), "l"(b));
}
__device__ __forceinline__ float2 unpack2(ull v) {
    unsigned x, y;
    asm("mov.b64 {%0, %1}, %2;" : "=r"(x), "=r"(y) : "l"(v));
    float2 f; f.x = __uint_as_float(x); f.y = __uint_as_float(y); return f;
}
// ---------------- cp.async helpers ----------------
__device__ __forceinline__ void cpa4(uint32_t smem, const void* g, unsigned nbytes) {
    asm volatile("cp.async.ca.shared.global [%0], [%1], 4, %2;"
                 :: "r"(smem), "l"(g), "r"(nbytes));
}
__device__ __forceinline__ void cpa_commit() {
    asm volatile("cp.async.commit_group;" ::: "memory");
}
template<int N> __device__ __forceinline__ void cpa_wait() {
    asm volatile("cp.async.wait_group %0;" :: "n"(N) : "memory");
}

// ---------------- scratch (device globals) ----------------
__device__ float g_h1[(size_t)BB*32*28*28];
__device__ float g_h2[(size_t)BB*64*14*14];
__device__ float g_h3[(size_t)BB*128*7*7];
__device__ float g_z [(size_t)BB*64];
__device__ int   g_eidx[BB];
__device__ float g_dfc[(size_t)BB*32*7*7];
__device__ float g_dh1[(size_t)BB*64*14*14];
__device__ float g_dh2[(size_t)BB*32*28*28];

// ---------------- encoder conv1 (1->32, 28x28, relu) ----------------
__global__ void k_enc_conv1(const float* __restrict__ x, const float* __restrict__ w,
                            const float* __restrict__ b, float* __restrict__ out) {
    __shared__ float sin_[784];
    __shared__ float sw[288];
    __shared__ float sb[32];
    int n = blockIdx.x, tid = threadIdx.x;
    const float* xin = x + (size_t)n * 784;
    for (int i = tid; i < 784; i += 256) sin_[i] = xin[i];
    for (int i = tid; i < 288; i += 256) sw[i] = w[i];
    if (tid < 32) sb[tid] = b[tid];
    __syncthreads();
    for (int p = tid; p < 784; p += 256) {
        int oy = p / 28, ox = p % 28;
        float v[9];
#pragma unroll
        for (int ky = 0; ky < 3; ky++)
#pragma unroll
            for (int kx = 0; kx < 3; kx++) {
                int iy = oy - 1 + ky, ix = ox - 1 + kx;
                v[ky*3+kx] = (iy >= 0 && iy < 28 && ix >= 0 && ix < 28) ? sin_[iy*28+ix] : 0.f;
            }
        for (int co = 0; co < 32; co++) {
            float a = sb[co];
#pragma unroll
            for (int t = 0; t < 9; t++) a += v[t] * sw[co*9+t];
            out[((size_t)n*32 + co)*784 + p] = fmaxf(a, 0.f);
        }
    }
}

// ---------------- f32x2 conv; PPT pixels/thread amortize weight LDS ----------------
// ACT: 0=relu 1=elu 2=sigmoid
template<int CIN,int COUT,int CO_B,int OH,int OW,int SH,int SW_,int STRIDE,int UP,int ACT,
         int NT,int PPT,int SB,int CI_T,int MINB>
__global__ void __launch_bounds__(NT, MINB)
conv6k(const float* __restrict__ in, const float* __restrict__ wt,
       const float* __restrict__ bs, float* __restrict__ out, const int* __restrict__ eidx) {
    constexpr int PW_ = SW_ + 2, PH_ = SH + 2, PA = PW_ * PH_;
    constexpr int NPIX = OH * OW, CO2 = CO_B / 2;
    constexpr int TILES = CIN / CI_T;
    constexpr int NBUF = (TILES > 1) ? 2 : 1;
    constexpr int TSZ = SB * CI_T * PA;
    static_assert(NT * PPT == SB * NPIX, "coverage");
    static_assert(CIN % CI_T == 0, "citile");
    static_assert(((NBUF * TSZ) & 1) == 0, "align8");

    extern __shared__ ull dsm[];
    float* sp = (float*)dsm;                              // NBUF * TSZ floats
    ull* sw2 = dsm + (size_t)(NBUF * TSZ) / 2;            // CIN*9*CO2 ulls
    __shared__ float sbias[CO_B];

    const int tid = threadIdx.x;
    const int nb = blockIdx.x * SB;
    const int cob = blockIdx.y;
    const float* wb = wt;
    const float* bb = bs;
    if (eidx) { int e = eidx[nb]; wb += (size_t)e * COUT * CIN * 9; bb += (size_t)e * COUT; }

    // stage packed weights ONCE: sw2[(ci*9+t)*CO2 + c2]
    for (int i = tid; i < CIN * 9 * CO2; i += NT) {
        int ci = i / (9 * CO2); int r = i - ci * 9 * CO2;
        int t = r / CO2; int c2 = r - t * CO2;
        int c0 = cob * CO_B + 2 * c2;
        float w0 = wb[((size_t)c0 * CIN + ci) * 9 + t];
        float w1 = wb[((size_t)(c0 + 1) * CIN + ci) * 9 + t];
        sw2[(ci * 9 + t) * CO2 + c2] = pack2(w0, w1);
    }
    if (tid < CO_B) sbias[tid] = bb[cob * CO_B + tid];

    // per-thread pixel setup
    int aoff[PPT], sbase[PPT], sArr[PPT], pixArr[PPT];
    bool pyA[PPT], pxA[PPT];
#pragma unroll
    for (int pp = 0; pp < PPT; pp++) {
        int p = tid + pp * NT;
        int s = p / NPIX; int pix = p - s * NPIX;
        int oy = pix / OW, ox = pix - oy * OW;
        if (UP) {
            aoff[pp] = (((oy - 1) >> 1) + 1) * PW_ + (((ox - 1) >> 1) + 1);
            pyA[pp] = (oy & 1) != 0;
            pxA[pp] = (ox & 1) != 0;
        } else {
            aoff[pp] = oy * STRIDE * PW_ + ox * STRIDE;
            pyA[pp] = pxA[pp] = false;
        }
        sbase[pp] = s * CI_T * PA;
        sArr[pp] = s; pixArr[pp] = pix;
    }

    ull acc[PPT][CO2];
#pragma unroll
    for (int pp = 0; pp < PPT; pp++)
#pragma unroll
        for (int c2 = 0; c2 < CO2; c2++) acc[pp][c2] = 0ull;

    auto prefetch = [&](int ci0, int b) {
        uint32_t sbuf = (uint32_t)__cvta_generic_to_shared(sp + (size_t)b * TSZ);
        for (int i = tid; i < TSZ; i += NT) {
            int ss = i / (CI_T * PA); int r = i - ss * (CI_T * PA);
            int ci = r / PA; int q = r - ci * PA;
            int py = q / PW_, px = q - py * PW_;
            int iy = py - 1, ix = px - 1;
            bool ok = (iy >= 0) & (iy < SH) & (ix >= 0) & (ix < SW_);
            const float* g = &in[(((size_t)(nb + ss) * CIN + ci0 + ci) * SH + (ok ? iy : 0)) * SW_ + (ok ? ix : 0)];
            cpa4(sbuf + (uint32_t)i * 4u, g, ok ? 4u : 0u);
        }
        cpa_commit();
    };

    prefetch(0, 0);
    for (int t = 0; t < TILES; t++) {
        if (t + 1 < TILES) { prefetch((t + 1) * CI_T, (t + 1) % NBUF); cpa_wait<1>(); }
        else               { cpa_wait<0>(); }
        __syncthreads();
        const float* buf = sp + (size_t)(t % NBUF) * TSZ;
#pragma unroll 1
        for (int ci = 0; ci < CI_T; ci++) {
            const ull* wrow = sw2 + (size_t)((t * CI_T + ci) * 9) * CO2;
            float tv[PPT][9];
#pragma unroll
            for (int pp = 0; pp < PPT; pp++) {
                const float* cb = buf + sbase[pp] + ci * PA;
                if (UP) {
                    float a = cb[aoff[pp]], b2_ = cb[aoff[pp] + 1];
                    float c = cb[aoff[pp] + PW_], d = cb[aoff[pp] + PW_ + 1];
                    tv[pp][0] = a;
                    tv[pp][1] = pxA[pp] ? a : b2_;
                    tv[pp][2] = b2_;
                    tv[pp][3] = pyA[pp] ? a : c;
                    tv[pp][4] = pyA[pp] ? (pxA[pp] ? a : b2_) : (pxA[pp] ? c : d);
                    tv[pp][5] = pyA[pp] ? b2_ : d;
                    tv[pp][6] = c;
                    tv[pp][7] = pxA[pp] ? c : d;
                    tv[pp][8] = d;
                } else {
#pragma unroll
                    for (int ky = 0; ky < 3; ky++)
#pragma unroll
                        for (int kx = 0; kx < 3; kx++)
                            tv[pp][ky*3+kx] = cb[aoff[pp] + ky * PW_ + kx];
                }
            }
#pragma unroll
            for (int t9 = 0; t9 < 9; t9++) {
                ull v2[PPT];
#pragma unroll
                for (int pp = 0; pp < PPT; pp++) v2[pp] = dup2(tv[pp][t9]);
                const ull* wt_ = wrow + t9 * CO2;
#pragma unroll
                for (int c2 = 0; c2 < CO2; c2++) {
                    ull wv = wt_[c2];
#pragma unroll
                    for (int pp = 0; pp < PPT; pp++) fma2(acc[pp][c2], v2[pp], wv);
                }
            }
        }
        if (t + 1 < TILES) __syncthreads();
    }

    // epilogue
#pragma unroll
    for (int pp = 0; pp < PPT; pp++) {
        int n = nb + sArr[pp]; int pix = pixArr[pp];
#pragma unroll
        for (int c2 = 0; c2 < CO2; c2++) {
            float2 f = unpack2(acc[pp][c2]);
            int c0 = cob * CO_B + 2 * c2;
            float r0 = f.x + sbias[2*c2];
            float r1 = f.y + sbias[2*c2+1];
            if (ACT == 0)      { r0 = fmaxf(r0, 0.f); r1 = fmaxf(r1, 0.f); }
            else if (ACT == 1) { r0 = r0 > 0.f ? r0 : expm1f(r0); r1 = r1 > 0.f ? r1 : expm1f(r1); }
            else               { r0 = 1.f/(1.f+expf(-r0)); r1 = 1.f/(1.f+expf(-r1)); }
            out[((size_t)n * COUT + c0) * NPIX + pix] = r0;
            out[((size_t)n * COUT + c0 + 1) * NPIX + pix] = r1;
        }
    }
}

// ---------------- fused mu+logvar fc: split-K=7, atomics ----------------
__global__ void __launch_bounds__(256)
k_fc2(const float* __restrict__ A,
      const float* __restrict__ Wm, const float* __restrict__ bm,
      const float* __restrict__ Wl, const float* __restrict__ bl,
      float* __restrict__ Om, float* __restrict__ Ol) {
    __shared__ float sa[32][33];
    __shared__ float swm[32][64];
    __shared__ float swl[32][64];
    int tid = threadIdx.x, tx = tid & 15, ty = tid >> 4;
    float am[2][4] = {}, al[2][4] = {};
    int row0 = blockIdx.x * 32;
    int k0 = blockIdx.y * 896;
    for (int it = 0; it < 28; it++) {
        int kb = k0 + it * 32;
        for (int i = tid; i < 32*32; i += 256) { int r = i>>5, c = i&31; sa[r][c] = A[(size_t)(row0+r)*6272 + kb + c]; }
        for (int i = tid; i < 32*64; i += 256) { int r = i>>6, c = i&63;
            swm[r][c] = Wm[(size_t)(kb+r)*64 + c];
            swl[r][c] = Wl[(size_t)(kb+r)*64 + c]; }
        __syncthreads();
#pragma unroll
        for (int kk = 0; kk < 32; kk++) {
            float a0 = sa[ty*2][kk], a1 = sa[ty*2+1][kk];
#pragma unroll
            for (int j = 0; j < 4; j++) {
                float wm_ = swm[kk][tx*4+j], wl_ = swl[kk][tx*4+j];
                am[0][j] += a0 * wm_; am[1][j] += a1 * wm_;
                al[0][j] += a0 * wl_; al[1][j] += a1 * wl_;
            }
        }
        __syncthreads();
    }
#pragma unroll
    for (int i = 0; i < 2; i++)
#pragma unroll
        for (int j = 0; j < 4; j++) {
            int r = row0 + ty*2 + i, c = tx*4 + j;
            float vm = am[i][j], vl = al[i][j];
            if (blockIdx.y == 0) { vm += bm[c]; vl += bl[c]; }
            atomicAdd(&Om[(size_t)r*64 + c], vm);
            atomicAdd(&Ol[(size_t)r*64 + c], vl);
        }
}

// ---------------- z sample + gating MLP + softmax + argmax ----------------
__global__ void __launch_bounds__(64)
k_gate(const float* __restrict__ mu, const float* __restrict__ lv, const float* __restrict__ eps,
       const float* __restrict__ w1, const float* __restrict__ b1,
       const float* __restrict__ w2, const float* __restrict__ b2,
       const float* __restrict__ w3, const float* __restrict__ b3,
       float* __restrict__ logits_out, float* __restrict__ probs_out) {
    int n = blockIdx.x, t = threadIdx.x;
    __shared__ float zz[64], h1[64], h2[32], lg[8];
    float m = mu[(size_t)n*64 + t], l = lv[(size_t)n*64 + t];
    float z = m + eps[(size_t)n*64 + t] * expf(0.5f * l);
    zz[t] = z;
    g_z[(size_t)n*64 + t] = z;
    __syncthreads();
    float a = b1[t];
    for (int k = 0; k < 64; k++) a += zz[k] * w1[k*64 + t];
    h1[t] = fmaxf(a, 0.f);
    __syncthreads();
    if (t < 32) {
        float a2 = b2[t];
        for (int k = 0; k < 64; k++) a2 += h1[k] * w2[k*32 + t];
        h2[t] = fmaxf(a2, 0.f);
    }
    __syncthreads();
    if (t < 8) {
        float a3 = b3[t];
        for (int k = 0; k < 32; k++) a3 += h2[k] * w3[k*8 + t];
        lg[t] = a3;
    }
    __syncthreads();
    if (t == 0) {
        float mx = lg[0];
        for (int i = 1; i < 8; i++) mx = fmaxf(mx, lg[i]);
        float e[8], s = 0.f;
        for (int i = 0; i < 8; i++) { e[i] = expf(lg[i] - mx); s += e[i]; }
        float inv = 1.f / s;
        int best = 0; float bp = -1.f;
        for (int i = 0; i < 8; i++) {
            float p = e[i] * inv;
            probs_out[(size_t)n*8 + i] = p;
            logits_out[(size_t)n*8 + i] = logf(p + 1e-8f);
            if (p > bp) { bp = p; best = i; }
        }
        g_eidx[n] = best;
    }
}

// ---------------- decoder fc (selected expert) ----------------
__global__ void __launch_bounds__(256)
k_dec_fc(const float* __restrict__ fcw, const float* __restrict__ fcb) {
    int n = blockIdx.x, t = threadIdx.x;
    __shared__ float zz[64];
    int e = g_eidx[n];
    if (t < 64) zz[t] = g_z[(size_t)n*64 + t];
    __syncthreads();
    const float* W = fcw + (size_t)e * 64 * 1568;
    const float* B = fcb + (size_t)e * 1568;
    for (int o = t; o < 1568; o += 256) {
        float a = B[o];
#pragma unroll 8
        for (int k = 0; k < 64; k++) a += zz[k] * W[(size_t)k*1568 + o];
        g_dfc[(size_t)n*1568 + o] = a;
    }
}

// ---------------- decoder conv3 (32->1, sigmoid) ----------------
__global__ void __launch_bounds__(196)
k_dconv3(const float* __restrict__ in, const float* __restrict__ wt,
         const float* __restrict__ bs, float* __restrict__ out, const int* __restrict__ eidx) {
    extern __shared__ float sp3[];   // 32*900
    __shared__ float sw[288];
    __shared__ float sb0;
    int n = blockIdx.x, tid = threadIdx.x;
    int e = eidx[n];
    const float* wb = wt + (size_t)e * 288;
    if (tid == 0) sb0 = bs[e];
    for (int i = tid; i < 288; i += 196) sw[i] = wb[i];
    const float* inn = in + (size_t)n * 32 * 784;
    for (int i = tid; i < 32*900; i += 196) {
        int ci = i / 900, q = i - ci*900;
        int py = q / 30, px = q - py*30;
        int iy = py - 1, ix = px - 1;
        float v = 0.f;
        if (iy >= 0 && iy < 28 && ix >= 0 && ix < 28) v = inn[ci*784 + iy*28 + ix];
        sp3[i] = v;
    }
    __syncthreads();
    int base[4]; int pixA[4];
#pragma unroll
    for (int pp = 0; pp < 4; pp++) {
        int p = tid + pp*196; pixA[pp] = p;
        int oy = p / 28, ox = p - oy*28;
        base[pp] = oy*30 + ox;
    }
    float acc[4] = {0.f, 0.f, 0.f, 0.f};
    for (int ci = 0; ci < 32; ci++) {
        float wr[9];
#pragma unroll
        for (int t = 0; t < 9; t++) wr[t] = sw[ci*9 + t];
        const float* cb = sp3 + ci*900;
#pragma unroll
        for (int ky = 0; ky < 3; ky++)
#pragma unroll
            for (int kx = 0; kx < 3; kx++) {
#pragma unroll
                for (int pp = 0; pp < 4; pp++)
                    acc[pp] += cb[base[pp] + ky*30 + kx] * wr[ky*3+kx];
            }
    }
#pragma unroll
    for (int pp = 0; pp < 4; pp++) {
        float r = acc[pp] + sb0;
        out[(size_t)n*784 + pixA[pp]] = 1.f / (1.f + expf(-r));
    }
}

// ---------------- launcher ----------------
extern "C" void kernel_launch(void* const* d_in, const int* in_sizes, int n_in,
                              void* d_out, int out_size) {
    const float* x      = (const float*)d_in[0];
    const float* eps    = (const float*)d_in[1];
    const float* enc_w1 = (const float*)d_in[2];  const float* enc_b1 = (const float*)d_in[3];
    const float* enc_w2 = (const float*)d_in[4];  const float* enc_b2 = (const float*)d_in[5];
    const float* enc_w3 = (const float*)d_in[6];  const float* enc_b3 = (const float*)d_in[7];
    const float* w_mu   = (const float*)d_in[8];  const float* b_mu   = (const float*)d_in[9];
    const float* w_lv   = (const float*)d_in[10]; const float* b_lv   = (const float*)d_in[11];
    const float* g_w1   = (const float*)d_in[12]; const float* g_b1   = (const float*)d_in[13];
    const float* g_w2   = (const float*)d_in[14]; const float* g_b2   = (const float*)d_in[15];
    const float* g_w3   = (const float*)d_in[16]; const float* g_b3   = (const float*)d_in[17];
    const float* d_fc_w = (const float*)d_in[18]; const float* d_fc_b = (const float*)d_in[19];
    const float* d_w1   = (const float*)d_in[20]; const float* d_b1   = (const float*)d_in[21];
    const float* d_w2   = (const float*)d_in[22]; const float* d_b2   = (const float*)d_in[23];
    const float* d_w3   = (const float*)d_in[24]; const float* d_b3   = (const float*)d_in[25];

    float* out   = (float*)d_out;
    float* o_rec = out;
    float* o_mu  = out + (size_t)BB*784;
    float* o_lv  = o_mu + (size_t)BB*64;
    float* o_lg  = o_lv + (size_t)BB*64;
    float* o_pb  = o_lg + (size_t)BB*8;

    float *h1, *h2, *h3, *dfc, *dh1, *dh2; int* eidx;
    cudaGetSymbolAddress((void**)&h1,  g_h1);
    cudaGetSymbolAddress((void**)&h2,  g_h2);
    cudaGetSymbolAddress((void**)&h3,  g_h3);
    cudaGetSymbolAddress((void**)&dfc, g_dfc);
    cudaGetSymbolAddress((void**)&dh1, g_dh1);
    cudaGetSymbolAddress((void**)&dh2, g_dh2);
    cudaGetSymbolAddress((void**)&eidx, g_eidx);

    // enc2: 32->64, 28->14 s2; NT=392, PPT=2, SB=4, CI_T=4, CO_B=16
    auto enc2 = conv6k<32,64,16, 14,14, 28,28, 2,0,0, 392,2,4,4,1>;
    constexpr int SM_ENC2 = 2*4*4*900*4 + 32*9*8*8;          // 115200+18432=133632
    // enc3: 64->128, 14->7 s2; NT=392, PPT=2, SB=16, CI_T=2, CO_B=16
    auto enc3 = conv6k<64,128,16, 7,7, 14,14, 2,0,0, 392,2,16,2,1>;
    constexpr int SM_ENC3 = 2*16*2*256*4 + 64*9*8*8;         // 65536+36864=102400
    // dec1: 32->64, up 7->14; NT=196, PPT=1, SB=1, single tile, CO_B=32
    auto dec1 = conv6k<32,64,32, 14,14, 7,7, 1,1,1, 196,1,1,32,4>;
    constexpr int SM_DEC1 = 1*32*81*4 + 32*9*16*8;           // 10368+36864=47232
    // dec2: 64->32, up 14->28; NT=392, PPT=2, SB=1, CI_T=32, CO_B=16
    auto dec2 = conv6k<64,32,16, 28,28, 14,14, 1,1,1, 392,2,1,32,1>;
    constexpr int SM_DEC2 = 2*1*32*256*4 + 64*9*8*8;         // 65536+36864=102400
    constexpr int SM_DEC3 = 32*900*4;                         // 115200

    cudaFuncSetAttribute(enc2, cudaFuncAttributeMaxDynamicSharedMemorySize, SM_ENC2);
    cudaFuncSetAttribute(enc3, cudaFuncAttributeMaxDynamicSharedMemorySize, SM_ENC3);
    cudaFuncSetAttribute(dec1, cudaFuncAttributeMaxDynamicSharedMemorySize, SM_DEC1);
    cudaFuncSetAttribute(dec2, cudaFuncAttributeMaxDynamicSharedMemorySize, SM_DEC2);
    cudaFuncSetAttribute(k_dconv3, cudaFuncAttributeMaxDynamicSharedMemorySize, SM_DEC3);

    // mu/lv accumulated with atomics -> zero first (d_out is poisoned)
    cudaMemsetAsync(o_mu, 0, (size_t)BB*128*sizeof(float));

    // encoder
    k_enc_conv1<<<BB, 256>>>(x, enc_w1, enc_b1, h1);
    enc2<<<dim3(BB/4, 4),  392, SM_ENC2>>>(h1, enc_w2, enc_b2, h2, nullptr);
    enc3<<<dim3(BB/16, 8), 392, SM_ENC3>>>(h2, enc_w3, enc_b3, h3, nullptr);

    // mu / log_var
    k_fc2<<<dim3(64, 7), 256>>>(h3, w_mu, b_mu, w_lv, b_lv, o_mu, o_lv);

    // gating + expert selection
    k_gate<<<BB, 64>>>(o_mu, o_lv, eps, g_w1, g_b1, g_w2, g_b2, g_w3, g_b3, o_lg, o_pb);

    // decoder: only the selected expert per sample
    k_dec_fc<<<BB, 256>>>(d_fc_w, d_fc_b);
    dec1<<<dim3(BB, 2), 196, SM_DEC1>>>(dfc, d_w1, d_b1, dh1, eidx);
    dec2<<<dim3(BB, 2), 392, SM_DEC2>>>(dh1, d_w2, d_b2, dh2, eidx);
    k_dconv3<<<BB, 196, SM_DEC3>>>(dh2, d_w3, d_b3, o_rec, eidx);
}